// round 1
// baseline (speedup 1.0000x reference)
#include <cuda_runtime.h>

#define BB   64
#define CC   256
#define DDIM 256
#define HW   784
#define ATTRN 300
#define O1   32

// scratch (device globals — no allocation allowed)
__device__ float g_sa[BB * DDIM];          // per-batch attr count-sketch
__device__ float g_CM[BB * O1 * DDIM];     // per-batch folded conv1 x circulant

// ---------------------------------------------------------------------------
// Kernel 1: emb = attr_oh @ W_emb^T + b_emb, then count-sketch with (h1, s1)
// grid = 64 blocks (one per batch), 256 threads (one per channel)
// ---------------------------------------------------------------------------
__global__ void __launch_bounds__(256) k1_sketch(
    const float* __restrict__ attr_oh,   // [B, ATTR]
    const float* __restrict__ W_emb,     // [C, ATTR]
    const float* __restrict__ b_emb,     // [C]
    const int*   __restrict__ h1,        // [C]
    const float* __restrict__ s1)        // [C]
{
    int b = blockIdx.x;
    int c = threadIdx.x;
    __shared__ float sh_attr[ATTRN];
    __shared__ float sa[DDIM];

    for (int i = c; i < ATTRN; i += 256) sh_attr[i] = attr_oh[b * ATTRN + i];
    sa[c] = 0.f;
    __syncthreads();

    float acc = b_emb[c];
    const float* wr = W_emb + c * ATTRN;
#pragma unroll 4
    for (int a = 0; a < ATTRN; a++) acc = fmaf(wr[a], sh_attr[a], acc);

    atomicAdd(&sa[h1[c]], s1[c] * acc);
    __syncthreads();
    g_sa[b * DDIM + c] = sa[c];
}

// ---------------------------------------------------------------------------
// Kernel 2: CM[b,o,m] = sum_j conv1_w[o, (m+j) & 255] * sa[b, j]
// grid = (8 m-groups, 64 batches), 256 threads; thread = (m in 32-group, 4 o's)
// ---------------------------------------------------------------------------
__global__ void __launch_bounds__(256) k2_cm(const float* __restrict__ conv1_w)
{
    int b = blockIdx.y;
    __shared__ float w1s[O1 * DDIM];   // 32 KB
    __shared__ float sas[DDIM];
    int tid = threadIdx.x;

    for (int i = tid; i < O1 * DDIM; i += 256) w1s[i] = conv1_w[i];
    sas[tid] = g_sa[b * DDIM + tid];
    __syncthreads();

    int m  = blockIdx.x * 32 + (tid & 31);
    int o0 = (tid >> 5) << 2;   // 4 consecutive output channels
    float a0 = 0.f, a1 = 0.f, a2 = 0.f, a3 = 0.f;

#pragma unroll 4
    for (int j = 0; j < DDIM; j++) {
        float sv  = sas[j];
        int   idx = (m + j) & (DDIM - 1);
        a0 = fmaf(w1s[(o0 + 0) * DDIM + idx], sv, a0);
        a1 = fmaf(w1s[(o0 + 1) * DDIM + idx], sv, a1);
        a2 = fmaf(w1s[(o0 + 2) * DDIM + idx], sv, a2);
        a3 = fmaf(w1s[(o0 + 3) * DDIM + idx], sv, a3);
    }

    float* cm = g_CM + (b * O1) * DDIM;
    cm[(o0 + 0) * DDIM + m] = a0;
    cm[(o0 + 1) * DDIM + m] = a1;
    cm[(o0 + 2) * DDIM + m] = a2;
    cm[(o0 + 3) * DDIM + m] = a3;
}

// ---------------------------------------------------------------------------
// Kernel 3: main fused GEMM + sigmoid gate + broadcast multiply
//   A[o,c] = s2[c] * CM[b,o,h2[c]]   (built in shared)
//   hidden[o,p] = relu(sum_c A[o,c] * x[b,c,p])
//   map[p] = sigmoid(sum_o w2[o] * hidden[o,p])
//   feat[c,p] = map[p] * x[b,c,p]
// grid = (4 position tiles, 64 batches), 256 threads
// thread = (quad of 4 positions, group of 8 output channels)
// ---------------------------------------------------------------------------
__global__ void __launch_bounds__(256) k3_main(
    const float* __restrict__ x,        // [B, C, HW]
    const int*   __restrict__ h2,       // [C]
    const float* __restrict__ s2,       // [C]
    const float* __restrict__ conv2_w,  // [32]
    float* __restrict__ out_map,        // [B, HW]
    float* __restrict__ out_feat)       // [B, C, HW]
{
    int b    = blockIdx.y;
    int tile = blockIdx.x;
    __shared__ float  A[O1 * CC];       // 32 KB
    __shared__ float4 red4[256];
    __shared__ float4 marr4[64];
    __shared__ float  w2s[O1];
    int tid = threadIdx.x;

    const float* cmb = g_CM + b * O1 * DDIM;
    for (int i = tid; i < O1 * CC; i += 256) {
        int o = i >> 8, c = i & 255;
        A[i] = s2[c] * cmb[(o << 8) + h2[c]];
    }
    if (tid < O1) w2s[tid] = conv2_w[tid];
    __syncthreads();

    int ql = tid & 63;          // local quad
    int og = tid >> 6;          // o-group 0..3 (8 channels each)
    int q  = tile * 64 + ql;    // global quad index (196 valid per batch)
    bool valid = q < (HW / 4);
    int p = q * 4;
    const float* xb = x + (size_t)b * CC * HW;

    float4 acc[8];
#pragma unroll
    for (int oo = 0; oo < 8; oo++) acc[oo] = make_float4(0.f, 0.f, 0.f, 0.f);

    if (valid) {
        const float* Abase = A + og * 8 * CC;
        for (int c = 0; c < CC; c++) {
            float4 xv = *(const float4*)(xb + c * HW + p);
#pragma unroll
            for (int oo = 0; oo < 8; oo++) {
                float av = Abase[oo * CC + c];   // warp-uniform broadcast
                acc[oo].x = fmaf(av, xv.x, acc[oo].x);
                acc[oo].y = fmaf(av, xv.y, acc[oo].y);
                acc[oo].z = fmaf(av, xv.z, acc[oo].z);
                acc[oo].w = fmaf(av, xv.w, acc[oo].w);
            }
        }
    }

    // relu + conv2 partial sum over this thread's 8 o's
    float4 ps = make_float4(0.f, 0.f, 0.f, 0.f);
#pragma unroll
    for (int oo = 0; oo < 8; oo++) {
        float w = w2s[og * 8 + oo];
        ps.x = fmaf(w, fmaxf(acc[oo].x, 0.f), ps.x);
        ps.y = fmaf(w, fmaxf(acc[oo].y, 0.f), ps.y);
        ps.z = fmaf(w, fmaxf(acc[oo].z, 0.f), ps.z);
        ps.w = fmaf(w, fmaxf(acc[oo].w, 0.f), ps.w);
    }
    red4[tid] = ps;
    __syncthreads();

    if (og == 0) {
        float4 t0 = red4[ql], t1 = red4[64 + ql], t2 = red4[128 + ql], t3 = red4[192 + ql];
        float4 t;
        t.x = t0.x + t1.x + t2.x + t3.x;
        t.y = t0.y + t1.y + t2.y + t3.y;
        t.z = t0.z + t1.z + t2.z + t3.z;
        t.w = t0.w + t1.w + t2.w + t3.w;
        float4 mm;
        mm.x = 1.f / (1.f + __expf(-t.x));
        mm.y = 1.f / (1.f + __expf(-t.y));
        mm.z = 1.f / (1.f + __expf(-t.z));
        mm.w = 1.f / (1.f + __expf(-t.w));
        marr4[ql] = mm;
        if (valid) *(float4*)(out_map + b * HW + p) = mm;
    }
    __syncthreads();

    // epilogue: feat = map * x  (x quad re-read hits L1/L2 — whole x fits L2)
    float* fb = out_feat + (size_t)b * CC * HW;
    for (int i = tid; i < CC * 64; i += 256) {
        int c  = i >> 6;
        int qq = i & 63;
        int qg = tile * 64 + qq;
        if (qg < (HW / 4)) {
            int pp = qg * 4;
            float4 xv = *(const float4*)(xb + c * HW + pp);
            float4 mm = marr4[qq];
            float4 r;
            r.x = mm.x * xv.x;
            r.y = mm.y * xv.y;
            r.z = mm.z * xv.z;
            r.w = mm.w * xv.w;
            *(float4*)(fb + c * HW + pp) = r;
        }
    }
}

// ---------------------------------------------------------------------------
extern "C" void kernel_launch(void* const* d_in, const int* in_sizes, int n_in,
                              void* d_out, int out_size)
{
    (void)in_sizes; (void)n_in; (void)out_size;
    const float* x        = (const float*)d_in[0];  // entity_feature [64,256,28,28]
    const float* attr_oh  = (const float*)d_in[1];  // [64,300]
    const float* W_emb    = (const float*)d_in[2];  // [256,300]
    const float* b_emb    = (const float*)d_in[3];  // [256]
    const int*   h1       = (const int*)  d_in[4];  // [256]
    const float* s1       = (const float*)d_in[5];  // [256]
    const int*   h2       = (const int*)  d_in[6];  // [256]
    const float* s2       = (const float*)d_in[7];  // [256]
    const float* conv1_w  = (const float*)d_in[8];  // [32,256]
    const float* conv2_w  = (const float*)d_in[9];  // [1,32]

    float* out      = (float*)d_out;
    float* out_map  = out;                  // [64,784]
    float* out_feat = out + BB * HW;        // [64,256,784]

    k1_sketch<<<BB, 256>>>(attr_oh, W_emb, b_emb, h1, s1);
    k2_cm<<<dim3(8, BB), 256>>>(conv1_w);
    k3_main<<<dim3(4, BB), 256>>>(x, h2, s2, conv2_w, out_map, out_feat);
}

// round 2
// speedup vs baseline: 1.2391x; 1.2391x over previous
#include <cuda_runtime.h>

#define BB    64
#define CC    256
#define DDIM  256
#define HW    784
#define ATTRN 300
#define O1    32
#define ASTR  257   // padded A row stride (floats) to spread og-step across banks

// scratch (device globals — no allocation allowed)
__device__ float g_sa[BB * DDIM];          // per-batch attr count-sketch
__device__ float g_CM[BB * O1 * DDIM];     // per-batch folded conv1 x circulant

// ---- packed f32x2 helpers -------------------------------------------------
__device__ __forceinline__ unsigned long long fma2(unsigned long long a,
                                                   unsigned long long b,
                                                   unsigned long long c) {
    unsigned long long d;
    asm("fma.rn.f32x2 %0, %1, %2, %3;" : "=l"(d) : "l"(a), "l"(b), "l"(c));
    return d;
}
__device__ __forceinline__ unsigned long long pack2(float x) {
    unsigned long long d;
    asm("mov.b64 %0, {%1, %1};" : "=l"(d) : "f"(x));
    return d;
}
__device__ __forceinline__ float2 unpk2(unsigned long long v) {
    float2 r;
    asm("mov.b64 {%0, %1}, %2;" : "=f"(r.x), "=f"(r.y) : "l"(v));
    return r;
}

// ---------------------------------------------------------------------------
// Kernel 1: emb = attr_oh @ W_emb^T + b_emb, count-sketch with (h1,s1).
// Warp-cooperative dot products: coalesced W_emb loads + shfl reduce.
// grid = 64 (batch), 256 threads = 8 warps
// ---------------------------------------------------------------------------
__global__ void __launch_bounds__(256) k1_sketch(
    const float* __restrict__ attr_oh,
    const float* __restrict__ W_emb,
    const float* __restrict__ b_emb,
    const int*   __restrict__ h1,
    const float* __restrict__ s1)
{
    int b = blockIdx.x;
    int tid = threadIdx.x;
    int w = tid >> 5, l = tid & 31;
    __shared__ float sh_attr[ATTRN];
    __shared__ float emb_s[CC];
    __shared__ float sa[DDIM];

    for (int i = tid; i < ATTRN; i += 256) sh_attr[i] = attr_oh[b * ATTRN + i];
    sa[tid] = 0.f;
    __syncthreads();

    // 8 warps, each handles 32 channels
    for (int c = w; c < CC; c += 8) {
        const float* wr = W_emb + c * ATTRN;
        float acc = 0.f;
        for (int a = l; a < ATTRN; a += 32) acc = fmaf(wr[a], sh_attr[a], acc);
#pragma unroll
        for (int off = 16; off; off >>= 1) acc += __shfl_xor_sync(0xffffffffu, acc, off);
        if (l == 0) emb_s[c] = acc + b_emb[c];
    }
    __syncthreads();

    atomicAdd(&sa[h1[tid]], s1[tid] * emb_s[tid]);
    __syncthreads();
    g_sa[b * DDIM + tid] = sa[tid];
}

// ---------------------------------------------------------------------------
// Kernel 2: CM[b,o,m] = sum_j conv1_w[o,(m+j)&255] * sa[b,j]
// 4 batches per block -> 16 FMA per 8 LDS (FMA-bound).
// grid = (8 m-tiles, 16 batch-groups), 256 threads
// ---------------------------------------------------------------------------
__global__ void __launch_bounds__(256) k2_cm(const float* __restrict__ conv1_w)
{
    int b0 = blockIdx.y * 4;
    __shared__ float w1s[O1 * DDIM];       // 32 KB
    __shared__ float sas[4][DDIM];         // 4 KB
    int tid = threadIdx.x;

    for (int i = tid; i < O1 * DDIM; i += 256) w1s[i] = conv1_w[i];
#pragma unroll
    for (int bi = 0; bi < 4; bi++) sas[bi][tid] = g_sa[(b0 + bi) * DDIM + tid];
    __syncthreads();

    int m  = blockIdx.x * 32 + (tid & 31);
    int o0 = (tid >> 5) << 2;
    float acc[4][4];
#pragma unroll
    for (int bi = 0; bi < 4; bi++)
#pragma unroll
        for (int oi = 0; oi < 4; oi++) acc[bi][oi] = 0.f;

#pragma unroll 4
    for (int j = 0; j < DDIM; j++) {
        int idx = (m + j) & (DDIM - 1);
        float w0 = w1s[(o0 + 0) * DDIM + idx];
        float w1 = w1s[(o0 + 1) * DDIM + idx];
        float w2 = w1s[(o0 + 2) * DDIM + idx];
        float w3 = w1s[(o0 + 3) * DDIM + idx];
        float v0 = sas[0][j], v1 = sas[1][j], v2 = sas[2][j], v3 = sas[3][j];
        acc[0][0] = fmaf(w0, v0, acc[0][0]); acc[0][1] = fmaf(w1, v0, acc[0][1]);
        acc[0][2] = fmaf(w2, v0, acc[0][2]); acc[0][3] = fmaf(w3, v0, acc[0][3]);
        acc[1][0] = fmaf(w0, v1, acc[1][0]); acc[1][1] = fmaf(w1, v1, acc[1][1]);
        acc[1][2] = fmaf(w2, v1, acc[1][2]); acc[1][3] = fmaf(w3, v1, acc[1][3]);
        acc[2][0] = fmaf(w0, v2, acc[2][0]); acc[2][1] = fmaf(w1, v2, acc[2][1]);
        acc[2][2] = fmaf(w2, v2, acc[2][2]); acc[2][3] = fmaf(w3, v2, acc[2][3]);
        acc[3][0] = fmaf(w0, v3, acc[3][0]); acc[3][1] = fmaf(w1, v3, acc[3][1]);
        acc[3][2] = fmaf(w2, v3, acc[3][2]); acc[3][3] = fmaf(w3, v3, acc[3][3]);
    }

#pragma unroll
    for (int bi = 0; bi < 4; bi++)
#pragma unroll
        for (int oi = 0; oi < 4; oi++)
            g_CM[((b0 + bi) * O1 + o0 + oi) * DDIM + m] = acc[bi][oi];
}

// ---------------------------------------------------------------------------
// Kernel 3: fused GEMM (FFMA2) + sigmoid gate + broadcast multiply
// grid = (7 tiles, 64 batches), 224 threads = 28 quads x 8 o-groups (4 o each)
// ---------------------------------------------------------------------------
__global__ void __launch_bounds__(224) k3_main(
    const float* __restrict__ x,        // [B, C, HW]
    const int*   __restrict__ h2,
    const float* __restrict__ s2,
    const float* __restrict__ conv2_w,  // [32]
    float* __restrict__ out_map,        // [B, HW]
    float* __restrict__ out_feat)       // [B, C, HW]
{
    int b    = blockIdx.y;
    int tile = blockIdx.x;
    __shared__ float  A[O1 * ASTR];     // ~32.9 KB, padded rows
    __shared__ float4 red4[224];
    __shared__ float4 marr4[28];
    __shared__ float  w2s[O1];
    int tid = threadIdx.x;
    int og = tid & 7;       // o-group 0..7 (4 channels each)
    int ql = tid >> 3;      // quad 0..27

    const float* cmb = g_CM + b * O1 * DDIM;
    for (int i = tid; i < O1 * CC; i += 224) {
        int o = i >> 8, c = i & 255;
        A[o * ASTR + c] = s2[c] * cmb[(o << 8) + h2[c]];
    }
    if (tid < O1) w2s[tid] = conv2_w[tid];
    __syncthreads();

    int q = tile * 28 + ql;             // 7*28 = 196 quads, all valid
    int p = q * 4;
    const float* xb = x + (size_t)b * CC * HW;

    unsigned long long acc2[4][2];
#pragma unroll
    for (int oo = 0; oo < 4; oo++) { acc2[oo][0] = 0ull; acc2[oo][1] = 0ull; }

    const float* Abase = A + (og * 4) * ASTR;
#pragma unroll 4
    for (int c = 0; c < CC; c++) {
        ulonglong2 xv = *(const ulonglong2*)(xb + (size_t)c * HW + p);
#pragma unroll
        for (int oo = 0; oo < 4; oo++) {
            unsigned long long av2 = pack2(Abase[oo * ASTR + c]);
            acc2[oo][0] = fma2(av2, xv.x, acc2[oo][0]);
            acc2[oo][1] = fma2(av2, xv.y, acc2[oo][1]);
        }
    }

    // relu + conv2 partial over this thread's 4 o's
    float4 ps = make_float4(0.f, 0.f, 0.f, 0.f);
#pragma unroll
    for (int oo = 0; oo < 4; oo++) {
        float w = w2s[og * 4 + oo];
        float2 lo = unpk2(acc2[oo][0]);
        float2 hi = unpk2(acc2[oo][1]);
        ps.x = fmaf(w, fmaxf(lo.x, 0.f), ps.x);
        ps.y = fmaf(w, fmaxf(lo.y, 0.f), ps.y);
        ps.z = fmaf(w, fmaxf(hi.x, 0.f), ps.z);
        ps.w = fmaf(w, fmaxf(hi.y, 0.f), ps.w);
    }
    red4[tid] = ps;
    __syncthreads();

    if (tid < 28) {
        float4 t = make_float4(0.f, 0.f, 0.f, 0.f);
#pragma unroll
        for (int g = 0; g < 8; g++) {
            float4 r = red4[tid * 8 + g];
            t.x += r.x; t.y += r.y; t.z += r.z; t.w += r.w;
        }
        float4 mm;
        mm.x = 1.f / (1.f + __expf(-t.x));
        mm.y = 1.f / (1.f + __expf(-t.y));
        mm.z = 1.f / (1.f + __expf(-t.z));
        mm.w = 1.f / (1.f + __expf(-t.w));
        marr4[tid] = mm;
        *(float4*)(out_map + b * HW + (tile * 28 + tid) * 4) = mm;
    }
    __syncthreads();

    // epilogue: feat = map * x (x re-read hits L2)
    float* fb = out_feat + (size_t)b * CC * HW;
    for (int i = tid; i < CC * 28; i += 224) {
        int c  = i / 28;
        int qq = i - c * 28;
        int pp = (tile * 28 + qq) * 4;
        float4 xv = *(const float4*)(xb + (size_t)c * HW + pp);
        float4 mm = marr4[qq];
        float4 r;
        r.x = mm.x * xv.x; r.y = mm.y * xv.y;
        r.z = mm.z * xv.z; r.w = mm.w * xv.w;
        *(float4*)(fb + (size_t)c * HW + pp) = r;
    }
}

// ---------------------------------------------------------------------------
extern "C" void kernel_launch(void* const* d_in, const int* in_sizes, int n_in,
                              void* d_out, int out_size)
{
    (void)in_sizes; (void)n_in; (void)out_size;
    const float* x        = (const float*)d_in[0];
    const float* attr_oh  = (const float*)d_in[1];
    const float* W_emb    = (const float*)d_in[2];
    const float* b_emb    = (const float*)d_in[3];
    const int*   h1       = (const int*)  d_in[4];
    const float* s1       = (const float*)d_in[5];
    const int*   h2       = (const int*)  d_in[6];
    const float* s2       = (const float*)d_in[7];
    const float* conv1_w  = (const float*)d_in[8];
    const float* conv2_w  = (const float*)d_in[9];

    float* out      = (float*)d_out;
    float* out_map  = out;               // [64,784]
    float* out_feat = out + BB * HW;     // [64,256,784]

    k1_sketch<<<BB, 256>>>(attr_oh, W_emb, b_emb, h1, s1);
    k2_cm<<<dim3(8, 16), 256>>>(conv1_w);
    k3_main<<<dim3(7, BB), 224>>>(x, h2, s2, conv2_w, out_map, out_feat);
}